// round 15
// baseline (speedup 1.0000x reference)
#include <cuda_runtime.h>
#include <cuda_fp16.h>
#include <cstdint>

#define HID 1024
#define SEQ 2048
#define BATCH 4
#define NHEADS 16
#define DH 64
#define MTOT (BATCH*SEQ)

// Q projection scale: 0.125 * log2(e), so attention S is in the log2 domain
#define QSCALE 0.18033688011112042f
#define ONE2 0x3C003C00u

// ---------------- scratch (static device arrays are allowed) ---------------
__device__ __half g_qh[MTOT*HID];
__device__ __half g_kh[MTOT*HID];
__device__ __half g_vh[MTOT*HID];
__device__ __half g_wqh[HID*HID];
__device__ __half g_wkh[HID*HID];
__device__ __half g_wvh[HID*HID];
__device__ __half g_woh[HID*HID];
__device__ __half g_Qp[MTOT*HID];
__device__ __half g_Kp[MTOT*HID];
__device__ __half g_Vt[BATCH*NHEADS*DH*SEQ];   // [b,h,d,s]
__device__ __half g_Hb[MTOT*HID];

// ---------------- helpers ---------------------------------------------------
__device__ __forceinline__ uint32_t smem_u32(const void* p){
    uint32_t a;
    asm("{ .reg .u64 t; cvta.to.shared.u64 t, %1; cvt.u32.u64 %0, t; }":"=r"(a):"l"(p));
    return a;
}
__device__ __forceinline__ void cp16(const void* dst, const void* src){
    asm volatile("cp.async.cg.shared.global [%0], [%1], 16;"
                 ::"r"(smem_u32(dst)),"l"(src));
}
#define CP_COMMIT() asm volatile("cp.async.commit_group;":::"memory")
#define CP_WAIT1()  asm volatile("cp.async.wait_group 1;":::"memory")
#define CP_WAIT0()  asm volatile("cp.async.wait_group 0;":::"memory")

// mma.sync m16n8k16 fp16 (sm_75+, legal on plain sm_103 target)
__device__ __forceinline__ void mma16(float* d, const uint32_t* a,
                                      uint32_t b0, uint32_t b1){
    asm volatile(
        "mma.sync.aligned.m16n8k16.row.col.f32.f16.f16.f32 "
        "{%0,%1,%2,%3}, {%4,%5,%6,%7}, {%8,%9}, {%0,%1,%2,%3};"
        : "+f"(d[0]),"+f"(d[1]),"+f"(d[2]),"+f"(d[3])
        : "r"(a[0]),"r"(a[1]),"r"(a[2]),"r"(a[3]),
          "r"(b0),"r"(b1));
}
// ldmatrix x4 (sm_75+)
__device__ __forceinline__ void ldm4(uint32_t* r, const void* p){
    asm volatile("ldmatrix.sync.aligned.m8n8.x4.shared.b16 {%0,%1,%2,%3}, [%4];"
        : "=r"(r[0]),"=r"(r[1]),"=r"(r[2]),"=r"(r[3]) : "r"(smem_u32(p)));
}
__device__ __forceinline__ uint32_t packh2(float x, float y){
    __half2 h = __floats2half2_rn(x, y);
    return *(uint32_t*)&h;
}
// packed fp16x2 exp2 (one MUFU op for two elements)
__device__ __forceinline__ uint32_t h2exp2u(uint32_t x){
    uint32_t r; asm("ex2.approx.f16x2 %0, %1;":"=r"(r):"r"(x)); return r;
}

// ---------------- fused fp32 -> fp16 conversions (one launch) ---------------
__global__ void tohalf_all(
    const float* __restrict__ q, const float* __restrict__ k, const float* __restrict__ v,
    const float* __restrict__ wq, const float* __restrict__ wk,
    const float* __restrict__ wv, const float* __restrict__ wo,
    __half* __restrict__ qh, __half* __restrict__ kh, __half* __restrict__ vh,
    __half* __restrict__ wqh, __half* __restrict__ wkh,
    __half* __restrict__ wvh, __half* __restrict__ woh)
{
    const int which = blockIdx.y;
    const float* s; __half* d; int n4;
    switch(which){
        case 0: s=q;  d=qh;  n4=MTOT*HID/4; break;
        case 1: s=k;  d=kh;  n4=MTOT*HID/4; break;
        case 2: s=v;  d=vh;  n4=MTOT*HID/4; break;
        case 3: s=wq; d=wqh; n4=HID*HID/4;  break;
        case 4: s=wk; d=wkh; n4=HID*HID/4;  break;
        case 5: s=wv; d=wvh; n4=HID*HID/4;  break;
        default:s=wo; d=woh; n4=HID*HID/4;  break;
    }
    int i = blockIdx.x*256 + threadIdx.x;
    if(i < n4){
        float4 vv = ((const float4*)s)[i];
        __half2* o = (__half2*)d + 2*i;
        o[0] = __floats2half2_rn(vv.x, vv.y);
        o[1] = __floats2half2_rn(vv.z, vv.w);
    }
}

// ---------------- warp-MMA GEMM: C = A @ W^T + bias (fp16 in, fp32 acc) -----
// Block 128x128, 8 warps (4x2), warp tile 32x64. K chunks of 64, double buffer.
// 2 CTAs/SM for latency hiding.
// modes: 0=Q(bias,*QSCALE,half) 1=K(half) 2=V(half, per-head transpose) 3=float
#define GH_SMEM (4*128*72*2)
__global__ __launch_bounds__(256,2) void gemm_hs(
    const __half* __restrict__ A0, const __half* __restrict__ A1, const __half* __restrict__ A2,
    const __half* __restrict__ W0, const __half* __restrict__ W1, const __half* __restrict__ W2,
    const float* __restrict__ b0, const float* __restrict__ b1, const float* __restrict__ b2,
    void* __restrict__ C0, void* __restrict__ C1, void* __restrict__ C2,
    int mode_in)
{
    extern __shared__ __half smh[];
    const int z = blockIdx.z;
    const __half* A    = (z==0)?A0:(z==1)?A1:A2;
    const __half* W    = (z==0)?W0:(z==1)?W1:W2;
    const float*  bias = (z==0)?b0:(z==1)?b1:b2;
    void*         C    = (z==0)?C0:(z==1)?C1:C2;
    const int mode = (mode_in < 0) ? z : mode_in;

    __half* As[2] = { smh,            smh + 128*72 };
    __half* Ws[2] = { smh + 2*128*72, smh + 3*128*72 };

    const int t    = threadIdx.x;
    const int w    = t >> 5;
    const int lane = t & 31;
    const int g    = lane >> 2;
    const int tig  = lane & 3;
    const int wm   = (w >> 1) * 32;
    const int wn   = (w & 1) * 64;
    const int m0   = blockIdx.y * 128;
    const int n0   = blockIdx.x * 128;

    // ldmatrix lane->address components
    const int aRow = wm + (lane & 15);
    const int aCol = (lane >> 4) * 8;
    const int bRow = wn + ((lane >> 4) & 1) * 8 + (lane & 7);
    const int bCol = ((lane >> 3) & 1) * 8;

    float acc[2][8][4];
#pragma unroll
    for(int mt=0;mt<2;mt++)
#pragma unroll
        for(int nt=0;nt<8;nt++)
#pragma unroll
            for(int i2=0;i2<4;i2++) acc[mt][nt][i2]=0.f;

    // prologue: chunk 0
#pragma unroll
    for(int i=0;i<4;i++){
        int s = t + 256*i; int r = s>>3, c8 = s&7;
        cp16(&As[0][r*72 + c8*8], A + (size_t)(m0+r)*HID + c8*8);
        cp16(&Ws[0][r*72 + c8*8], W + (size_t)(n0+r)*HID + c8*8);
    }
    CP_COMMIT();

    for(int c=0;c<16;c++){
        const int buf = c & 1;
        if(c+1 < 16){
            const int k0 = (c+1)*64, nb = (c+1)&1;
#pragma unroll
            for(int i=0;i<4;i++){
                int s = t + 256*i; int r = s>>3, c8 = s&7;
                cp16(&As[nb][r*72 + c8*8], A + (size_t)(m0+r)*HID + k0 + c8*8);
                cp16(&Ws[nb][r*72 + c8*8], W + (size_t)(n0+r)*HID + k0 + c8*8);
            }
            CP_COMMIT();
            CP_WAIT1();
        } else {
            CP_WAIT0();
        }
        __syncthreads();

        const __half* aBase = &As[buf][aRow*72 + aCol];
        const __half* bBase = &Ws[buf][bRow*72 + bCol];
#pragma unroll
        for(int k16=0;k16<4;k16++){
            const int kk = k16*16;
            uint32_t a[2][4];
            ldm4(a[0], aBase + kk);
            ldm4(a[1], aBase + 16*72 + kk);
#pragma unroll
            for(int p=0;p<4;p++){
                uint32_t bb[4];
                ldm4(bb, bBase + p*16*72 + kk);
#pragma unroll
                for(int mt=0;mt<2;mt++){
                    mma16(acc[mt][2*p],   a[mt], bb[0], bb[1]);
                    mma16(acc[mt][2*p+1], a[mt], bb[2], bb[3]);
                }
            }
        }
        __syncthreads();
    }

    // epilogue
#pragma unroll
    for(int mt=0;mt<2;mt++){
        const int row0 = m0 + wm + mt*16 + g;
        const int row1 = row0 + 8;
#pragma unroll
        for(int nt=0;nt<8;nt++){
            const int col0 = n0 + wn + nt*8 + 2*tig;
            const float bb0 = bias[col0], bb1 = bias[col0+1];
            float v00 = acc[mt][nt][0] + bb0, v01 = acc[mt][nt][1] + bb1;
            float v10 = acc[mt][nt][2] + bb0, v11 = acc[mt][nt][3] + bb1;
            if(mode==0){ v00*=QSCALE; v01*=QSCALE; v10*=QSCALE; v11*=QSCALE; }
            if(mode==2){
                __half* Ch = (__half*)C;
                const int bb = row0 >> 11;
                const int s0 = row0 & 2047, s1 = row1 & 2047;
                const int h0 = col0 >> 6,  d0 = col0 & 63;
                const int h1 = (col0+1) >> 6, d1 = (col0+1) & 63;
                Ch[((size_t)(bb*NHEADS+h0)*DH + d0)*SEQ + s0] = __float2half_rn(v00);
                Ch[((size_t)(bb*NHEADS+h1)*DH + d1)*SEQ + s0] = __float2half_rn(v01);
                Ch[((size_t)(bb*NHEADS+h0)*DH + d0)*SEQ + s1] = __float2half_rn(v10);
                Ch[((size_t)(bb*NHEADS+h1)*DH + d1)*SEQ + s1] = __float2half_rn(v11);
            } else if(mode==3){
                float* Cf = (float*)C;
                *(float2*)&Cf[(size_t)row0*HID + col0] = make_float2(v00, v01);
                *(float2*)&Cf[(size_t)row1*HID + col0] = make_float2(v10, v11);
            } else {
                __half* Ch = (__half*)C;
                *(__half2*)&Ch[(size_t)row0*HID + col0] = __floats2half2_rn(v00, v01);
                *(__half2*)&Ch[(size_t)row1*HID + col0] = __floats2half2_rn(v10, v11);
            }
        }
    }
}

// ---------------- warp-MMA attention (fp16, packed exp2, ones-MMA lsum) -----
// CTA = one (b,h) x 128 queries; 8 warps x 16 rows. 128-key tiles, K/V dbl-buf.
// S in two 64-key halves; P = ex2.f16x2(S) (Q pre-scaled by 0.125*log2e);
// row sums accumulated by an extra all-ones MMA (fp32 accum, same P values).
#define AH_SMEM ((128*72 + 2*128*72 + 2*64*136)*2)
__global__ __launch_bounds__(256,2) void attn_hs(
    const __half* __restrict__ Qp, const __half* __restrict__ Kp,
    const __half* __restrict__ Vt, const int* __restrict__ mask,
    __half* __restrict__ Hb)
{
    extern __shared__ __half smh[];
    __half* Qs    = smh;                       // [128][72]
    __half* Ks[2] = { smh + 128*72, smh + 2*128*72 };
    __half* Vs[2] = { smh + 3*128*72, smh + 3*128*72 + 64*136 };

    const int t    = threadIdx.x;
    const int w    = t >> 5;
    const int lane = t & 31;
    const int g    = lane >> 2;
    const int tig  = lane & 3;
    const int bh = blockIdx.y;
    const int b  = bh >> 4, h = bh & 15;
    const int q0 = blockIdx.x * 128;

    // ldmatrix lane->address components
    const int aRow = w*16 + (lane & 15);                  // A-role rows (Q)
    const int aCol = (lane >> 4) * 8;
    const int bRow = ((lane >> 4) & 1) * 8 + (lane & 7);  // B-role rows (K, V)
    const int bCol = ((lane >> 3) & 1) * 8;

    // load Q tile + K/V tile 0 in one group
#pragma unroll
    for(int i=0;i<4;i++){
        int s = t + 256*i; int r = s>>3, c8 = s&7;
        cp16(&Qs[r*72 + c8*8], Qp + (size_t)(b*SEQ + q0 + r)*HID + h*DH + c8*8);
        cp16(&Ks[0][r*72 + c8*8], Kp + (size_t)(b*SEQ + r)*HID + h*DH + c8*8);
    }
#pragma unroll
    for(int i=0;i<4;i++){
        int s = t + 256*i; int d = s>>4, c8 = s&15;
        cp16(&Vs[0][d*136 + c8*8], Vt + ((size_t)(b*NHEADS+h)*DH + d)*SEQ + c8*8);
    }
    CP_COMMIT();

    const int row0g = q0 + w*16 + g;
    const int m0v = mask[b*SEQ + row0g];
    const int m1v = mask[b*SEQ + row0g + 8];

    float o[8][4];
#pragma unroll
    for(int nt=0;nt<8;nt++)
#pragma unroll
        for(int i2=0;i2<4;i2++) o[nt][i2]=0.f;
    float ls[4] = {0.f, 0.f, 0.f, 0.f};   // row sums via ones-MMA

    uint32_t aq[4][4];

    for(int kt=0; kt<16; kt++){
        const int buf = kt & 1;
        if(kt+1 < 16){
            const int nb = buf ^ 1;
            const size_t krow = (size_t)(b*SEQ + (kt+1)*128);
#pragma unroll
            for(int i=0;i<4;i++){
                int s = t + 256*i; int r = s>>3, c8 = s&7;
                cp16(&Ks[nb][r*72 + c8*8], Kp + (krow + r)*HID + h*DH + c8*8);
            }
#pragma unroll
            for(int i=0;i<4;i++){
                int s = t + 256*i; int d = s>>4, c8 = s&15;
                cp16(&Vs[nb][d*136 + c8*8],
                     Vt + ((size_t)(b*NHEADS+h)*DH + d)*SEQ + (kt+1)*128 + c8*8);
            }
            CP_COMMIT();
            CP_WAIT1();
        } else {
            CP_WAIT0();
        }
        __syncthreads();

        if(kt==0){
            const __half* qBase = &Qs[aRow*72 + aCol];
#pragma unroll
            for(int k16=0;k16<4;k16++) ldm4(aq[k16], qBase + k16*16);
        }

        // process the 128-key tile as two 64-key halves (keeps s4 at 32 regs)
#pragma unroll
        for(int half=0; half<2; half++){
            // S = Q @ K^T for 64 keys (log2-domain); warp computes 16x64
            float s4[8][4];
#pragma unroll
            for(int nt=0;nt<8;nt++)
#pragma unroll
                for(int i2=0;i2<4;i2++) s4[nt][i2]=0.f;
            const __half* kBase = &Ks[buf][(half*64 + bRow)*72 + bCol];
#pragma unroll
            for(int k16=0;k16<4;k16++){
                const int kk = k16*16;
#pragma unroll
                for(int p=0;p<4;p++){
                    uint32_t bb[4];
                    ldm4(bb, kBase + p*16*72 + kk);
                    mma16(s4[2*p],   aq[k16], bb[0], bb[1]);
                    mma16(s4[2*p+1], aq[k16], bb[2], bb[3]);
                }
            }

            // O += exp2(S) @ V for these 64 keys; packed fp16x2 exp2.
            const __half* vBase = &Vs[buf][bRow*136 + bCol + half*64];
#pragma unroll
            for(int k16=0;k16<4;k16++){
                uint32_t ap[4];
                ap[0] = m0v ? h2exp2u(packh2(s4[2*k16][0],   s4[2*k16][1]))   : ONE2;
                ap[1] = m1v ? h2exp2u(packh2(s4[2*k16][2],   s4[2*k16][3]))   : ONE2;
                ap[2] = m0v ? h2exp2u(packh2(s4[2*k16+1][0], s4[2*k16+1][1])) : ONE2;
                ap[3] = m1v ? h2exp2u(packh2(s4[2*k16+1][2], s4[2*k16+1][3])) : ONE2;
                // row sums of P (exactly the values used in PV)
                mma16(ls, ap, ONE2, ONE2);
                const int kk = k16*16;
#pragma unroll
                for(int p=0;p<4;p++){
                    uint32_t bb[4];
                    ldm4(bb, vBase + p*16*136 + kk);
                    mma16(o[2*p],   ap, bb[0], bb[1]);
                    mma16(o[2*p+1], ap, bb[2], bb[3]);
                }
            }
        }
        __syncthreads();
    }

    const float inv0 = 1.f / ls[0];
    const float inv1 = 1.f / ls[2];

    // write O (fp16: feeds the output projection)
    const size_t r0 = (size_t)(b*SEQ + row0g)*HID + h*DH;
    const size_t r1 = r0 + 8*HID;
#pragma unroll
    for(int nt=0;nt<8;nt++){
        const int cc = nt*8 + 2*tig;
        *(__half2*)&Hb[r0 + cc] = __floats2half2_rn(o[nt][0]*inv0, o[nt][1]*inv0);
        *(__half2*)&Hb[r1 + cc] = __floats2half2_rn(o[nt][2]*inv1, o[nt][3]*inv1);
    }
}

// ---------------------------------------------------------------------------

extern "C" void kernel_launch(void* const* d_in, const int* in_sizes, int n_in,
                              void* d_out, int out_size)
{
    const float* q    = (const float*)d_in[0];
    const float* k    = (const float*)d_in[1];
    const float* v    = (const float*)d_in[2];
    const int*   mask = (const int*)  d_in[3];
    const float* wq   = (const float*)d_in[4];
    const float* bq   = (const float*)d_in[5];
    const float* wk   = (const float*)d_in[6];
    const float* bk   = (const float*)d_in[7];
    const float* wv   = (const float*)d_in[8];
    const float* bv   = (const float*)d_in[9];
    const float* wo   = (const float*)d_in[10];
    const float* bo   = (const float*)d_in[11];
    float* out = (float*)d_out;

    __half *qh,*kh,*vh,*wqh,*wkh,*wvh,*woh,*Qp,*Kp,*Vt,*Hb;
    cudaGetSymbolAddress((void**)&qh,  g_qh);
    cudaGetSymbolAddress((void**)&kh,  g_kh);
    cudaGetSymbolAddress((void**)&vh,  g_vh);
    cudaGetSymbolAddress((void**)&wqh, g_wqh);
    cudaGetSymbolAddress((void**)&wkh, g_wkh);
    cudaGetSymbolAddress((void**)&wvh, g_wvh);
    cudaGetSymbolAddress((void**)&woh, g_woh);
    cudaGetSymbolAddress((void**)&Qp,  g_Qp);
    cudaGetSymbolAddress((void**)&Kp,  g_Kp);
    cudaGetSymbolAddress((void**)&Vt,  g_Vt);
    cudaGetSymbolAddress((void**)&Hb,  g_Hb);

    cudaFuncSetAttribute(gemm_hs, cudaFuncAttributeMaxDynamicSharedMemorySize, GH_SMEM);
    cudaFuncSetAttribute(attn_hs, cudaFuncAttributeMaxDynamicSharedMemorySize, AH_SMEM);

    // 0. convert inputs + weights to fp16 (single launch)
    {
        dim3 gC(MTOT*HID/4/256, 7);
        tohalf_all<<<gC, 256>>>(q, k, v, wq, wk, wv, wo,
                                qh, kh, vh, wqh, wkh, wvh, woh);
    }

    // 1. fused QKV projections (z: 0=Q scaled, 1=K, 2=V transposed per-head)
    dim3 gQKV(HID/128, MTOT/128, 3);
    gemm_hs<<<gQKV, 256, GH_SMEM>>>(qh, kh, vh, wqh, wkh, wvh, bq, bk, bv,
                                    Qp, Kp, Vt, -1);

    // 2. attention
    dim3 gF(SEQ/128, BATCH*NHEADS);
    attn_hs<<<gF, 256, AH_SMEM>>>(Qp, Kp, Vt, mask, Hb);

    // 3. output projection (fp32 out)
    dim3 gO(HID/128, MTOT/128, 1);
    gemm_hs<<<gO, 256, GH_SMEM>>>(Hb, Hb, Hb, woh, woh, woh, bo, bo, bo,
                                  out, out, out, 3);
}

// round 16
// speedup vs baseline: 1.5108x; 1.5108x over previous
#include <cuda_runtime.h>
#include <cuda_fp16.h>
#include <cstdint>

#define HID 1024
#define SEQ 2048
#define BATCH 4
#define NHEADS 16
#define DH 64
#define MTOT (BATCH*SEQ)

// Q projection scale: 0.125 * log2(e), so attention S is in the log2 domain
#define QSCALE 0.18033688011112042f
#define ONE2 0x3C003C00u

// ---------------- scratch (static device arrays are allowed) ---------------
__device__ __half g_qh[MTOT*HID];
__device__ __half g_kh[MTOT*HID];
__device__ __half g_vh[MTOT*HID];
__device__ __half g_wqh[HID*HID];
__device__ __half g_wkh[HID*HID];
__device__ __half g_wvh[HID*HID];
__device__ __half g_woh[HID*HID];
__device__ __half g_Qp[MTOT*HID];
__device__ __half g_Kp[MTOT*HID];
__device__ __half g_Vt[BATCH*NHEADS*DH*SEQ];   // [b,h,d,s]
__device__ __half g_Hb[MTOT*HID];

// ---------------- helpers ---------------------------------------------------
__device__ __forceinline__ uint32_t smem_u32(const void* p){
    uint32_t a;
    asm("{ .reg .u64 t; cvta.to.shared.u64 t, %1; cvt.u32.u64 %0, t; }":"=r"(a):"l"(p));
    return a;
}
__device__ __forceinline__ void cp16(const void* dst, const void* src){
    asm volatile("cp.async.cg.shared.global [%0], [%1], 16;"
                 ::"r"(smem_u32(dst)),"l"(src));
}
#define CP_COMMIT() asm volatile("cp.async.commit_group;":::"memory")
#define CP_WAIT1()  asm volatile("cp.async.wait_group 1;":::"memory")
#define CP_WAIT0()  asm volatile("cp.async.wait_group 0;":::"memory")

// mma.sync m16n8k16 fp16 (sm_75+, legal on plain sm_103 target)
__device__ __forceinline__ void mma16(float* d, const uint32_t* a,
                                      uint32_t b0, uint32_t b1){
    asm volatile(
        "mma.sync.aligned.m16n8k16.row.col.f32.f16.f16.f32 "
        "{%0,%1,%2,%3}, {%4,%5,%6,%7}, {%8,%9}, {%0,%1,%2,%3};"
        : "+f"(d[0]),"+f"(d[1]),"+f"(d[2]),"+f"(d[3])
        : "r"(a[0]),"r"(a[1]),"r"(a[2]),"r"(a[3]),
          "r"(b0),"r"(b1));
}
// ldmatrix x4 (sm_75+)
__device__ __forceinline__ void ldm4(uint32_t* r, const void* p){
    asm volatile("ldmatrix.sync.aligned.m8n8.x4.shared.b16 {%0,%1,%2,%3}, [%4];"
        : "=r"(r[0]),"=r"(r[1]),"=r"(r[2]),"=r"(r[3]) : "r"(smem_u32(p)));
}
__device__ __forceinline__ uint32_t packh2(float x, float y){
    __half2 h = __floats2half2_rn(x, y);
    return *(uint32_t*)&h;
}
// packed fp16x2 exp2 (one MUFU op for two elements)
__device__ __forceinline__ uint32_t h2exp2u(uint32_t x){
    uint32_t r; asm("ex2.approx.f16x2 %0, %1;":"=r"(r):"r"(x)); return r;
}

// ---------------- fused fp32 -> fp16 conversions (one launch) ---------------
__global__ void tohalf_all(
    const float* __restrict__ q, const float* __restrict__ k, const float* __restrict__ v,
    const float* __restrict__ wq, const float* __restrict__ wk,
    const float* __restrict__ wv, const float* __restrict__ wo,
    __half* __restrict__ qh, __half* __restrict__ kh, __half* __restrict__ vh,
    __half* __restrict__ wqh, __half* __restrict__ wkh,
    __half* __restrict__ wvh, __half* __restrict__ woh)
{
    const int which = blockIdx.y;
    const float* s; __half* d; int n4;
    switch(which){
        case 0: s=q;  d=qh;  n4=MTOT*HID/4; break;
        case 1: s=k;  d=kh;  n4=MTOT*HID/4; break;
        case 2: s=v;  d=vh;  n4=MTOT*HID/4; break;
        case 3: s=wq; d=wqh; n4=HID*HID/4;  break;
        case 4: s=wk; d=wkh; n4=HID*HID/4;  break;
        case 5: s=wv; d=wvh; n4=HID*HID/4;  break;
        default:s=wo; d=woh; n4=HID*HID/4;  break;
    }
    int i = blockIdx.x*256 + threadIdx.x;
    if(i < n4){
        float4 vv = ((const float4*)s)[i];
        __half2* o = (__half2*)d + 2*i;
        o[0] = __floats2half2_rn(vv.x, vv.y);
        o[1] = __floats2half2_rn(vv.z, vv.w);
    }
}

// ---------------- warp-MMA GEMM: C = A @ W^T + bias (fp16 in, fp32 acc) -----
// Block 128x128, 8 warps (4x2), warp tile 32x64. K chunks of 64, double buffer.
// 2 CTAs/SM for latency hiding.
// modes: 0=Q(bias,*QSCALE,half) 1=K(half) 2=V(half, per-head transpose) 3=float
#define GH_SMEM (4*128*72*2)
__global__ __launch_bounds__(256,2) void gemm_hs(
    const __half* __restrict__ A0, const __half* __restrict__ A1, const __half* __restrict__ A2,
    const __half* __restrict__ W0, const __half* __restrict__ W1, const __half* __restrict__ W2,
    const float* __restrict__ b0, const float* __restrict__ b1, const float* __restrict__ b2,
    void* __restrict__ C0, void* __restrict__ C1, void* __restrict__ C2,
    int mode_in)
{
    extern __shared__ __half smh[];
    const int z = blockIdx.z;
    const __half* A    = (z==0)?A0:(z==1)?A1:A2;
    const __half* W    = (z==0)?W0:(z==1)?W1:W2;
    const float*  bias = (z==0)?b0:(z==1)?b1:b2;
    void*         C    = (z==0)?C0:(z==1)?C1:C2;
    const int mode = (mode_in < 0) ? z : mode_in;

    __half* As[2] = { smh,            smh + 128*72 };
    __half* Ws[2] = { smh + 2*128*72, smh + 3*128*72 };

    const int t    = threadIdx.x;
    const int w    = t >> 5;
    const int lane = t & 31;
    const int g    = lane >> 2;
    const int tig  = lane & 3;
    const int wm   = (w >> 1) * 32;
    const int wn   = (w & 1) * 64;
    const int m0   = blockIdx.y * 128;
    const int n0   = blockIdx.x * 128;

    // ldmatrix lane->address components
    const int aRow = wm + (lane & 15);
    const int aCol = (lane >> 4) * 8;
    const int bRow = wn + ((lane >> 4) & 1) * 8 + (lane & 7);
    const int bCol = ((lane >> 3) & 1) * 8;

    float acc[2][8][4];
#pragma unroll
    for(int mt=0;mt<2;mt++)
#pragma unroll
        for(int nt=0;nt<8;nt++)
#pragma unroll
            for(int i2=0;i2<4;i2++) acc[mt][nt][i2]=0.f;

    // prologue: chunk 0
#pragma unroll
    for(int i=0;i<4;i++){
        int s = t + 256*i; int r = s>>3, c8 = s&7;
        cp16(&As[0][r*72 + c8*8], A + (size_t)(m0+r)*HID + c8*8);
        cp16(&Ws[0][r*72 + c8*8], W + (size_t)(n0+r)*HID + c8*8);
    }
    CP_COMMIT();

    for(int c=0;c<16;c++){
        const int buf = c & 1;
        if(c+1 < 16){
            const int k0 = (c+1)*64, nb = (c+1)&1;
#pragma unroll
            for(int i=0;i<4;i++){
                int s = t + 256*i; int r = s>>3, c8 = s&7;
                cp16(&As[nb][r*72 + c8*8], A + (size_t)(m0+r)*HID + k0 + c8*8);
                cp16(&Ws[nb][r*72 + c8*8], W + (size_t)(n0+r)*HID + k0 + c8*8);
            }
            CP_COMMIT();
            CP_WAIT1();
        } else {
            CP_WAIT0();
        }
        __syncthreads();

        const __half* aBase = &As[buf][aRow*72 + aCol];
        const __half* bBase = &Ws[buf][bRow*72 + bCol];
#pragma unroll
        for(int k16=0;k16<4;k16++){
            const int kk = k16*16;
            uint32_t a[2][4];
            ldm4(a[0], aBase + kk);
            ldm4(a[1], aBase + 16*72 + kk);
#pragma unroll
            for(int p=0;p<4;p++){
                uint32_t bb[4];
                ldm4(bb, bBase + p*16*72 + kk);
#pragma unroll
                for(int mt=0;mt<2;mt++){
                    mma16(acc[mt][2*p],   a[mt], bb[0], bb[1]);
                    mma16(acc[mt][2*p+1], a[mt], bb[2], bb[3]);
                }
            }
        }
        __syncthreads();
    }

    // epilogue
#pragma unroll
    for(int mt=0;mt<2;mt++){
        const int row0 = m0 + wm + mt*16 + g;
        const int row1 = row0 + 8;
#pragma unroll
        for(int nt=0;nt<8;nt++){
            const int col0 = n0 + wn + nt*8 + 2*tig;
            const float bb0 = bias[col0], bb1 = bias[col0+1];
            float v00 = acc[mt][nt][0] + bb0, v01 = acc[mt][nt][1] + bb1;
            float v10 = acc[mt][nt][2] + bb0, v11 = acc[mt][nt][3] + bb1;
            if(mode==0){ v00*=QSCALE; v01*=QSCALE; v10*=QSCALE; v11*=QSCALE; }
            if(mode==2){
                __half* Ch = (__half*)C;
                const int bb = row0 >> 11;
                const int s0 = row0 & 2047, s1 = row1 & 2047;
                const int h0 = col0 >> 6,  d0 = col0 & 63;
                const int h1 = (col0+1) >> 6, d1 = (col0+1) & 63;
                Ch[((size_t)(bb*NHEADS+h0)*DH + d0)*SEQ + s0] = __float2half_rn(v00);
                Ch[((size_t)(bb*NHEADS+h1)*DH + d1)*SEQ + s0] = __float2half_rn(v01);
                Ch[((size_t)(bb*NHEADS+h0)*DH + d0)*SEQ + s1] = __float2half_rn(v10);
                Ch[((size_t)(bb*NHEADS+h1)*DH + d1)*SEQ + s1] = __float2half_rn(v11);
            } else if(mode==3){
                float* Cf = (float*)C;
                *(float2*)&Cf[(size_t)row0*HID + col0] = make_float2(v00, v01);
                *(float2*)&Cf[(size_t)row1*HID + col0] = make_float2(v10, v11);
            } else {
                __half* Ch = (__half*)C;
                *(__half2*)&Ch[(size_t)row0*HID + col0] = __floats2half2_rn(v00, v01);
                *(__half2*)&Ch[(size_t)row1*HID + col0] = __floats2half2_rn(v10, v11);
            }
        }
    }
}

// ---------------- warp-MMA attention (fp16, packed exp2, ones-MMA lsum) -----
// CTA = one (b,h) x 128 queries; 8 warps x 16 rows. 128-key tiles, K/V dbl-buf.
// S in two 64-key halves; P = ex2.f16x2(S) (Q pre-scaled by 0.125*log2e);
// row sums accumulated by an extra all-ones MMA (fp32 accum, same P values).
#define AH_SMEM ((128*72 + 2*128*72 + 2*64*136)*2)
__global__ __launch_bounds__(256,2) void attn_hs(
    const __half* __restrict__ Qp, const __half* __restrict__ Kp,
    const __half* __restrict__ Vt, const int* __restrict__ mask,
    __half* __restrict__ Hb)
{
    extern __shared__ __half smh[];
    __half* Qs    = smh;                       // [128][72]
    __half* Ks[2] = { smh + 128*72, smh + 2*128*72 };
    __half* Vs[2] = { smh + 3*128*72, smh + 3*128*72 + 64*136 };

    const int t    = threadIdx.x;
    const int w    = t >> 5;
    const int lane = t & 31;
    const int g    = lane >> 2;
    const int tig  = lane & 3;
    const int bh = blockIdx.y;
    const int b  = bh >> 4, h = bh & 15;
    const int q0 = blockIdx.x * 128;

    // ldmatrix lane->address components
    const int aRow = w*16 + (lane & 15);                  // A-role rows (Q)
    const int aCol = (lane >> 4) * 8;
    const int bRow = ((lane >> 4) & 1) * 8 + (lane & 7);  // B-role rows (K, V)
    const int bCol = ((lane >> 3) & 1) * 8;

    // load Q tile + K/V tile 0 in one group
#pragma unroll
    for(int i=0;i<4;i++){
        int s = t + 256*i; int r = s>>3, c8 = s&7;
        cp16(&Qs[r*72 + c8*8], Qp + (size_t)(b*SEQ + q0 + r)*HID + h*DH + c8*8);
        cp16(&Ks[0][r*72 + c8*8], Kp + (size_t)(b*SEQ + r)*HID + h*DH + c8*8);
    }
#pragma unroll
    for(int i=0;i<4;i++){
        int s = t + 256*i; int d = s>>4, c8 = s&15;
        cp16(&Vs[0][d*136 + c8*8], Vt + ((size_t)(b*NHEADS+h)*DH + d)*SEQ + c8*8);
    }
    CP_COMMIT();

    const int row0g = q0 + w*16 + g;
    const int m0v = mask[b*SEQ + row0g];
    const int m1v = mask[b*SEQ + row0g + 8];

    float o[8][4];
#pragma unroll
    for(int nt=0;nt<8;nt++)
#pragma unroll
        for(int i2=0;i2<4;i2++) o[nt][i2]=0.f;
    float ls[4] = {0.f, 0.f, 0.f, 0.f};   // row sums via ones-MMA

    uint32_t aq[4][4];

    for(int kt=0; kt<16; kt++){
        const int buf = kt & 1;
        if(kt+1 < 16){
            const int nb = buf ^ 1;
            const size_t krow = (size_t)(b*SEQ + (kt+1)*128);
#pragma unroll
            for(int i=0;i<4;i++){
                int s = t + 256*i; int r = s>>3, c8 = s&7;
                cp16(&Ks[nb][r*72 + c8*8], Kp + (krow + r)*HID + h*DH + c8*8);
            }
#pragma unroll
            for(int i=0;i<4;i++){
                int s = t + 256*i; int d = s>>4, c8 = s&15;
                cp16(&Vs[nb][d*136 + c8*8],
                     Vt + ((size_t)(b*NHEADS+h)*DH + d)*SEQ + (kt+1)*128 + c8*8);
            }
            CP_COMMIT();
            CP_WAIT1();
        } else {
            CP_WAIT0();
        }
        __syncthreads();

        if(kt==0){
            const __half* qBase = &Qs[aRow*72 + aCol];
#pragma unroll
            for(int k16=0;k16<4;k16++) ldm4(aq[k16], qBase + k16*16);
        }

        // process the 128-key tile as two 64-key halves (keeps s4 at 32 regs)
#pragma unroll
        for(int half=0; half<2; half++){
            // S = Q @ K^T for 64 keys (log2-domain); warp computes 16x64
            float s4[8][4];
#pragma unroll
            for(int nt=0;nt<8;nt++)
#pragma unroll
                for(int i2=0;i2<4;i2++) s4[nt][i2]=0.f;
            const __half* kBase = &Ks[buf][(half*64 + bRow)*72 + bCol];
#pragma unroll
            for(int k16=0;k16<4;k16++){
                const int kk = k16*16;
#pragma unroll
                for(int p=0;p<4;p++){
                    uint32_t bb[4];
                    ldm4(bb, kBase + p*16*72 + kk);
                    mma16(s4[2*p],   aq[k16], bb[0], bb[1]);
                    mma16(s4[2*p+1], aq[k16], bb[2], bb[3]);
                }
            }

            // O += exp2(S) @ V for these 64 keys; packed fp16x2 exp2.
            const __half* vBase = &Vs[buf][bRow*136 + bCol + half*64];
#pragma unroll
            for(int k16=0;k16<4;k16++){
                uint32_t ap[4];
                ap[0] = m0v ? h2exp2u(packh2(s4[2*k16][0],   s4[2*k16][1]))   : ONE2;
                ap[1] = m1v ? h2exp2u(packh2(s4[2*k16][2],   s4[2*k16][3]))   : ONE2;
                ap[2] = m0v ? h2exp2u(packh2(s4[2*k16+1][0], s4[2*k16+1][1])) : ONE2;
                ap[3] = m1v ? h2exp2u(packh2(s4[2*k16+1][2], s4[2*k16+1][3])) : ONE2;
                const int kk = k16*16;
                // PV MMAs first (critical path), ones-MMA for row sums last
#pragma unroll
                for(int p=0;p<4;p++){
                    uint32_t bb[4];
                    ldm4(bb, vBase + p*16*136 + kk);
                    mma16(o[2*p],   ap, bb[0], bb[1]);
                    mma16(o[2*p+1], ap, bb[2], bb[3]);
                }
                mma16(ls, ap, ONE2, ONE2);
            }
        }
        __syncthreads();
    }

    const float inv0 = 1.f / ls[0];
    const float inv1 = 1.f / ls[2];

    // write O (fp16: feeds the output projection)
    const size_t r0 = (size_t)(b*SEQ + row0g)*HID + h*DH;
    const size_t r1 = r0 + 8*HID;
#pragma unroll
    for(int nt=0;nt<8;nt++){
        const int cc = nt*8 + 2*tig;
        *(__half2*)&Hb[r0 + cc] = __floats2half2_rn(o[nt][0]*inv0, o[nt][1]*inv0);
        *(__half2*)&Hb[r1 + cc] = __floats2half2_rn(o[nt][2]*inv1, o[nt][3]*inv1);
    }
}

// ---------------------------------------------------------------------------

extern "C" void kernel_launch(void* const* d_in, const int* in_sizes, int n_in,
                              void* d_out, int out_size)
{
    const float* q    = (const float*)d_in[0];
    const float* k    = (const float*)d_in[1];
    const float* v    = (const float*)d_in[2];
    const int*   mask = (const int*)  d_in[3];
    const float* wq   = (const float*)d_in[4];
    const float* bq   = (const float*)d_in[5];
    const float* wk   = (const float*)d_in[6];
    const float* bk   = (const float*)d_in[7];
    const float* wv   = (const float*)d_in[8];
    const float* bv   = (const float*)d_in[9];
    const float* wo   = (const float*)d_in[10];
    const float* bo   = (const float*)d_in[11];
    float* out = (float*)d_out;

    __half *qh,*kh,*vh,*wqh,*wkh,*wvh,*woh,*Qp,*Kp,*Vt,*Hb;
    cudaGetSymbolAddress((void**)&qh,  g_qh);
    cudaGetSymbolAddress((void**)&kh,  g_kh);
    cudaGetSymbolAddress((void**)&vh,  g_vh);
    cudaGetSymbolAddress((void**)&wqh, g_wqh);
    cudaGetSymbolAddress((void**)&wkh, g_wkh);
    cudaGetSymbolAddress((void**)&wvh, g_wvh);
    cudaGetSymbolAddress((void**)&woh, g_woh);
    cudaGetSymbolAddress((void**)&Qp,  g_Qp);
    cudaGetSymbolAddress((void**)&Kp,  g_Kp);
    cudaGetSymbolAddress((void**)&Vt,  g_Vt);
    cudaGetSymbolAddress((void**)&Hb,  g_Hb);

    cudaFuncSetAttribute(gemm_hs, cudaFuncAttributeMaxDynamicSharedMemorySize, GH_SMEM);
    cudaFuncSetAttribute(attn_hs, cudaFuncAttributeMaxDynamicSharedMemorySize, AH_SMEM);

    // 0. convert inputs + weights to fp16 (single launch)
    {
        dim3 gC(MTOT*HID/4/256, 7);
        tohalf_all<<<gC, 256>>>(q, k, v, wq, wk, wv, wo,
                                qh, kh, vh, wqh, wkh, wvh, woh);
    }

    // 1. fused QKV projections (z: 0=Q scaled, 1=K, 2=V transposed per-head)
    dim3 gQKV(HID/128, MTOT/128, 3);
    gemm_hs<<<gQKV, 256, GH_SMEM>>>(qh, kh, vh, wqh, wkh, wvh, bq, bk, bv,
                                    Qp, Kp, Vt, -1);

    // 2. attention
    dim3 gF(SEQ/128, BATCH*NHEADS);
    attn_hs<<<gF, 256, AH_SMEM>>>(Qp, Kp, Vt, mask, Hb);

    // 3. output projection (fp32 out)
    dim3 gO(HID/128, MTOT/128, 1);
    gemm_hs<<<gO, 256, GH_SMEM>>>(Hb, Hb, Hb, woh, woh, woh, bo, bo, bo,
                                  out, out, out, 3);
}